// round 1
// baseline (speedup 1.0000x reference)
#include <cuda_runtime.h>

#define D_    1024
#define H_    768
#define HS_   1536
#define E_    8
#define TMAX  2048

// ---------------- static device scratch (no dynamic allocation allowed) ----------------
__device__ int   g_counts[E_];
__device__ int   g_offs[E_ + 1];
__device__ int   g_cursor[E_];
__device__ int   g_top[TMAX * 2];
__device__ float g_wgt[TMAX * 2];
__device__ int   g_bucket[TMAX * 2];
__device__ float g_bw[TMAX * 2];
__device__ float g_actR[TMAX * 2 * H_];        // routed activations per assignment
__device__ float g_actS[TMAX * HS_];           // shared-expert activations per token

// ---------------- kernel 0: zero counters ----------------
__global__ void k_zero() {
    if (threadIdx.x < E_) g_counts[threadIdx.x] = 0;
}

// ---------------- kernel 1: gate (softmax + top2) + expert counts ----------------
__global__ void k_gate(const float* __restrict__ x, const float* __restrict__ gw, int T) {
    __shared__ float sg[E_ * D_];   // 32 KB
    const float4* gw4 = (const float4*)gw;
    float4* sg4 = (float4*)sg;
    for (int i = threadIdx.x; i < E_ * D_ / 4; i += blockDim.x) sg4[i] = gw4[i];
    __syncthreads();

    int wid = threadIdx.x >> 5, lane = threadIdx.x & 31;
    int t = blockIdx.x * 8 + wid;
    if (t >= T) return;

    float acc[E_];
#pragma unroll
    for (int e = 0; e < E_; e++) acc[e] = 0.f;
    const float4* xr = (const float4*)(x + (size_t)t * D_);
    for (int i = lane; i < D_ / 4; i += 32) {
        float4 xv = xr[i];
#pragma unroll
        for (int e = 0; e < E_; e++) {
            float4 g = sg4[e * (D_ / 4) + i];
            acc[e] += xv.x * g.x + xv.y * g.y + xv.z * g.z + xv.w * g.w;
        }
    }
#pragma unroll
    for (int e = 0; e < E_; e++)
#pragma unroll
        for (int o = 16; o > 0; o >>= 1) acc[e] += __shfl_xor_sync(0xffffffffu, acc[e], o);

    if (lane == 0) {
        float m = acc[0];
#pragma unroll
        for (int e = 1; e < E_; e++) m = fmaxf(m, acc[e]);
        float p[E_]; float s = 0.f;
#pragma unroll
        for (int e = 0; e < E_; e++) { p[e] = __expf(acc[e] - m); s += p[e]; }
        float inv = 1.f / s;
#pragma unroll
        for (int e = 0; e < E_; e++) p[e] *= inv;
        // top-2 (first index wins ties, matching lax.top_k stable order)
        int i0 = 0; float v0 = p[0];
#pragma unroll
        for (int e = 1; e < E_; e++) if (p[e] > v0) { v0 = p[e]; i0 = e; }
        int i1 = -1; float v1 = -1.f;
#pragma unroll
        for (int e = 0; e < E_; e++) if (e != i0 && p[e] > v1) { v1 = p[e]; i1 = e; }
        g_top[t * 2] = i0;  g_top[t * 2 + 1] = i1;
        g_wgt[t * 2] = v0;  g_wgt[t * 2 + 1] = v1;
        atomicAdd(&g_counts[i0], 1);
        atomicAdd(&g_counts[i1], 1);
    }
}

// ---------------- kernel 2: prefix offsets (tiny) ----------------
__global__ void k_offs() {
    if (threadIdx.x == 0) {
        int s = 0;
        for (int e = 0; e < E_; e++) { g_offs[e] = s; s += g_counts[e]; g_cursor[e] = 0; }
        g_offs[E_] = s;
    }
}

// ---------------- kernel 3: scatter tokens into expert buckets ----------------
__global__ void k_scatter(int T) {
    int i = blockIdx.x * blockDim.x + threadIdx.x;
    if (i >= T * 2) return;
    int t = i >> 1;
    int e = g_top[i];
    int pos = atomicAdd(&g_cursor[e], 1);
    int idx = g_offs[e] + pos;
    g_bucket[idx] = t;
    g_bw[idx] = g_wgt[i];
    (void)t;
}

// ---------------- fc1 (+ gated SiLU): A = (X W_y^T) * silu(X W_g^T) ----------------
// ROUTED: W layout [E][2*hid][D], rows gathered by bucket -> g_actR
// shared: W = Ws1 [2*hid][D], identity rows               -> g_actS
template <bool ROUTED>
__global__ void k_fc1(const float* __restrict__ X, const float* __restrict__ Wb,
                      int T, int hid) {
    const int BM = 64, BN = 64, BK = 16;
    __shared__ float Xs[BK][BM];
    __shared__ float By[BK][BN];
    __shared__ float Bg[BK][BN];
    __shared__ int   toks[BM];

    int mcount, rbase;
    const float* W;
    float* Ab;
    if (ROUTED) {
        int e = blockIdx.z;
        rbase = g_offs[e];
        mcount = g_offs[e + 1] - rbase;
        W = Wb + (size_t)e * 2 * hid * D_;
        Ab = g_actR;
    } else {
        mcount = T; rbase = 0; W = Wb; Ab = g_actS;
    }
    int m0 = blockIdx.x * BM;
    if (m0 >= mcount) return;
    int n0 = blockIdx.y * BN;
    int tid = threadIdx.x;

    if (tid < BM) {
        int r = m0 + tid;
        if (r > mcount - 1) r = mcount - 1;
        toks[tid] = ROUTED ? g_bucket[rbase + r] : r;
    }
    __syncthreads();

    int ty = tid >> 4, tx = tid & 15;
    int lr = tid >> 2, lc = (tid & 3) * 4;
    float accY[4][4], accG[4][4];
#pragma unroll
    for (int i = 0; i < 4; i++)
#pragma unroll
        for (int j = 0; j < 4; j++) { accY[i][j] = 0.f; accG[i][j] = 0.f; }

    const float* xrow = X + (size_t)toks[lr] * D_ + lc;
    const float* wy = W + (size_t)(n0 + lr) * D_ + lc;
    const float* wg = W + (size_t)(hid + n0 + lr) * D_ + lc;

    for (int kk = 0; kk < D_; kk += BK) {
        float4 xv = *(const float4*)(xrow + kk);
        float4 yv = *(const float4*)(wy + kk);
        float4 gv = *(const float4*)(wg + kk);
        __syncthreads();
        Xs[lc + 0][lr] = xv.x; Xs[lc + 1][lr] = xv.y; Xs[lc + 2][lr] = xv.z; Xs[lc + 3][lr] = xv.w;
        By[lc + 0][lr] = yv.x; By[lc + 1][lr] = yv.y; By[lc + 2][lr] = yv.z; By[lc + 3][lr] = yv.w;
        Bg[lc + 0][lr] = gv.x; Bg[lc + 1][lr] = gv.y; Bg[lc + 2][lr] = gv.z; Bg[lc + 3][lr] = gv.w;
        __syncthreads();
#pragma unroll
        for (int k = 0; k < BK; k++) {
            float4 a = *(const float4*)&Xs[k][ty * 4];
            float4 b = *(const float4*)&By[k][tx * 4];
            float4 c = *(const float4*)&Bg[k][tx * 4];
            float av[4] = {a.x, a.y, a.z, a.w};
            float bv[4] = {b.x, b.y, b.z, b.w};
            float cv[4] = {c.x, c.y, c.z, c.w};
#pragma unroll
            for (int i = 0; i < 4; i++)
#pragma unroll
                for (int j = 0; j < 4; j++) {
                    accY[i][j] += av[i] * bv[j];
                    accG[i][j] += av[i] * cv[j];
                }
        }
    }

    int rrem = mcount - m0;
#pragma unroll
    for (int i = 0; i < 4; i++) {
        int r = ty * 4 + i;
        if (r < rrem) {
            size_t base = (size_t)(rbase + m0 + r) * hid + n0 + tx * 4;
#pragma unroll
            for (int j = 0; j < 4; j++) {
                float yv = accY[i][j], gv = accG[i][j];
                float sgm = 1.f / (1.f + __expf(-gv));
                Ab[base + j] = yv * (gv * sgm);
            }
        }
    }
}

// ---------------- fc2: out = A W2^T  (routed: *weight, atomicAdd; shared: plain store) ----------------
template <bool ROUTED>
__global__ void k_fc2(const float* __restrict__ Wb, float* __restrict__ out,
                      int T, int hid) {
    const int BM = 64, BN = 64, BK = 16;
    __shared__ float As[BK][BM];
    __shared__ float Bs[BK][BN];

    int mcount, rbase;
    const float* W;
    const float* Ain;
    if (ROUTED) {
        int e = blockIdx.z;
        rbase = g_offs[e];
        mcount = g_offs[e + 1] - rbase;
        W = Wb + (size_t)e * D_ * hid;
        Ain = g_actR;
    } else {
        mcount = T; rbase = 0; W = Wb; Ain = g_actS;
    }
    int m0 = blockIdx.x * BM;
    if (m0 >= mcount) return;
    int n0 = blockIdx.y * BN;
    int tid = threadIdx.x;
    int ty = tid >> 4, tx = tid & 15;
    int lr = tid >> 2, lc = (tid & 3) * 4;

    float acc[4][4];
#pragma unroll
    for (int i = 0; i < 4; i++)
#pragma unroll
        for (int j = 0; j < 4; j++) acc[i][j] = 0.f;

    int ar = m0 + lr;
    if (ar > mcount - 1) ar = mcount - 1;
    const float* arow = Ain + (size_t)(rbase + ar) * hid + lc;
    const float* wrow = W + (size_t)(n0 + lr) * hid + lc;

    for (int kk = 0; kk < hid; kk += BK) {
        float4 av = *(const float4*)(arow + kk);
        float4 bv = *(const float4*)(wrow + kk);
        __syncthreads();
        As[lc + 0][lr] = av.x; As[lc + 1][lr] = av.y; As[lc + 2][lr] = av.z; As[lc + 3][lr] = av.w;
        Bs[lc + 0][lr] = bv.x; Bs[lc + 1][lr] = bv.y; Bs[lc + 2][lr] = bv.z; Bs[lc + 3][lr] = bv.w;
        __syncthreads();
#pragma unroll
        for (int k = 0; k < BK; k++) {
            float4 a = *(const float4*)&As[k][ty * 4];
            float4 b = *(const float4*)&Bs[k][tx * 4];
            float av2[4] = {a.x, a.y, a.z, a.w};
            float bv2[4] = {b.x, b.y, b.z, b.w};
#pragma unroll
            for (int i = 0; i < 4; i++)
#pragma unroll
                for (int j = 0; j < 4; j++) acc[i][j] += av2[i] * bv2[j];
        }
    }

    int rrem = mcount - m0;
#pragma unroll
    for (int i = 0; i < 4; i++) {
        int r = ty * 4 + i;
        if (r < rrem) {
            if (ROUTED) {
                int t = g_bucket[rbase + m0 + r];
                float w = g_bw[rbase + m0 + r];
                size_t ob = (size_t)t * D_ + n0 + tx * 4;
#pragma unroll
                for (int j = 0; j < 4; j++) atomicAdd(&out[ob + j], w * acc[i][j]);
            } else {
                size_t ob = (size_t)(m0 + r) * D_ + n0 + tx * 4;
#pragma unroll
                for (int j = 0; j < 4; j++) out[ob + j] = acc[i][j];
            }
        }
    }
}

// ---------------- launcher ----------------
extern "C" void kernel_launch(void* const* d_in, const int* in_sizes, int n_in,
                              void* d_out, int out_size) {
    const float* x   = (const float*)d_in[0];
    const float* gw  = (const float*)d_in[1];
    const float* W1  = (const float*)d_in[2];
    const float* W2  = (const float*)d_in[3];
    const float* Ws1 = (const float*)d_in[4];
    const float* Ws2 = (const float*)d_in[5];
    float* out = (float*)d_out;

    int T = in_sizes[0] / D_;
    if (T > TMAX) T = TMAX;
    int mtiles = (T + 63) / 64;

    k_zero<<<1, 32>>>();
    k_gate<<<(T + 7) / 8, 256>>>(x, gw, T);
    k_offs<<<1, 32>>>();
    k_scatter<<<(T * 2 + 255) / 256, 256>>>(T);

    // fc1: routed (hidden 768) and shared (hidden 1536)
    k_fc1<true ><<<dim3(mtiles, H_  / 64, E_), 256>>>(x, W1,  T, H_);
    k_fc1<false><<<dim3(mtiles, HS_ / 64),     256>>>(x, Ws1, T, HS_);

    // fc2: shared writes out fully (plain store), then routed atomically accumulates
    k_fc2<false><<<dim3(mtiles, D_ / 64),     256>>>(Ws2, out, T, HS_);
    k_fc2<true ><<<dim3(mtiles, D_ / 64, E_), 256>>>(W2,  out, T, H_);
}

// round 2
// speedup vs baseline: 2.5270x; 2.5270x over previous
#include <cuda_runtime.h>
#include <cuda_bf16.h>
#include <stdint.h>

#define D_    1024
#define H_    768
#define HS_   1536
#define E_    8
#define TMAX  2048
#define AMAX  (TMAX*2)

#define KSZ   32
#define STR   40                      // smem row stride in bf16 elems (80B, conflict-free for ldmatrix)
#define STAGE_ELEMS (4*128*STR)       // Ah, Al, Bh, Bl tiles per stage
#define SMEM_BYTES  (2*STAGE_ELEMS*2) // 2 stages, 2B/elem = 81920

// ---------------- routing scratch ----------------
__device__ int   g_counts[E_];
__device__ int   g_offs[E_ + 1];
__device__ int   g_cursor[E_];
__device__ int   g_top[AMAX];
__device__ float g_wgt[AMAX];
__device__ int   g_bucket[AMAX];
__device__ float g_bw[AMAX];

// ---------------- bf16 hi/lo operand scratch ----------------
__device__ __nv_bfloat16 g_xh[TMAX * D_],       g_xl[TMAX * D_];
__device__ __nv_bfloat16 g_W1h[E_ * 2 * H_ * D_], g_W1l[E_ * 2 * H_ * D_];
__device__ __nv_bfloat16 g_W2h[E_ * D_ * H_],     g_W2l[E_ * D_ * H_];
__device__ __nv_bfloat16 g_S1h[2 * HS_ * D_],     g_S1l[2 * HS_ * D_];
__device__ __nv_bfloat16 g_S2h[D_ * HS_],         g_S2l[D_ * HS_];
__device__ __nv_bfloat16 g_aRh[AMAX * H_],        g_aRl[AMAX * H_];
__device__ __nv_bfloat16 g_aSh[TMAX * HS_],       g_aSl[TMAX * HS_];

// ---------------- PTX helpers ----------------
__device__ __forceinline__ uint32_t cvta_s(const void* p) {
    return (uint32_t)__cvta_generic_to_shared(p);
}
#define CPA(dst, src) asm volatile("cp.async.cg.shared.global [%0], [%1], 16;\n" :: "r"(dst), "l"(src))
#define CPC() asm volatile("cp.async.commit_group;\n")
#define CPW1() asm volatile("cp.async.wait_group 1;\n")
#define CPW0() asm volatile("cp.async.wait_group 0;\n")
#define LDM4(r0, r1, r2, r3, a) \
    asm volatile("ldmatrix.sync.aligned.m8n8.x4.shared.b16 {%0,%1,%2,%3}, [%4];" \
        : "=r"(r0), "=r"(r1), "=r"(r2), "=r"(r3) : "r"(a))
#define MMA(c, a, b) \
    asm volatile("mma.sync.aligned.m16n8k16.row.col.f32.bf16.bf16.f32 " \
        "{%0,%1,%2,%3},{%4,%5,%6,%7},{%8,%9},{%0,%1,%2,%3};" \
        : "+f"(c[0]), "+f"(c[1]), "+f"(c[2]), "+f"(c[3]) \
        : "r"(a[0]), "r"(a[1]), "r"(a[2]), "r"(a[3]), "r"(b[0]), "r"(b[1]))

// ---------------- conversion: fp32 -> bf16 hi + lo ----------------
__global__ void k_cvt(const float* __restrict__ src, __nv_bfloat16* __restrict__ hi,
                      __nv_bfloat16* __restrict__ lo, int n4) {
    int i = blockIdx.x * blockDim.x + threadIdx.x;
    if (i >= n4) return;
    float4 v = ((const float4*)src)[i];
    float vv[4] = {v.x, v.y, v.z, v.w};
    uint32_t ph[2], pl[2];
#pragma unroll
    for (int p = 0; p < 2; p++) {
        uint32_t a = 0, b = 0;
#pragma unroll
        for (int j = 0; j < 2; j++) {
            float f = vv[p * 2 + j];
            __nv_bfloat16 h = __float2bfloat16(f);
            __nv_bfloat16 l = __float2bfloat16(f - __bfloat162float(h));
            a |= (uint32_t)__bfloat16_as_ushort(h) << (16 * j);
            b |= (uint32_t)__bfloat16_as_ushort(l) << (16 * j);
        }
        ph[p] = a; pl[p] = b;
    }
    ((uint2*)hi)[i] = make_uint2(ph[0], ph[1]);
    ((uint2*)lo)[i] = make_uint2(pl[0], pl[1]);
}

// ---------------- gate pipeline (fp32, unchanged from R1) ----------------
__global__ void k_zero() {
    if (threadIdx.x < E_) g_counts[threadIdx.x] = 0;
}

__global__ void k_gate(const float* __restrict__ x, const float* __restrict__ gw, int T) {
    __shared__ float sg[E_ * D_];
    const float4* gw4 = (const float4*)gw;
    float4* sg4 = (float4*)sg;
    for (int i = threadIdx.x; i < E_ * D_ / 4; i += blockDim.x) sg4[i] = gw4[i];
    __syncthreads();

    int wid = threadIdx.x >> 5, lane = threadIdx.x & 31;
    int t = blockIdx.x * 8 + wid;
    if (t >= T) return;

    float acc[E_];
#pragma unroll
    for (int e = 0; e < E_; e++) acc[e] = 0.f;
    const float4* xr = (const float4*)(x + (size_t)t * D_);
    for (int i = lane; i < D_ / 4; i += 32) {
        float4 xv = xr[i];
#pragma unroll
        for (int e = 0; e < E_; e++) {
            float4 g = sg4[e * (D_ / 4) + i];
            acc[e] += xv.x * g.x + xv.y * g.y + xv.z * g.z + xv.w * g.w;
        }
    }
#pragma unroll
    for (int e = 0; e < E_; e++)
#pragma unroll
        for (int o = 16; o > 0; o >>= 1) acc[e] += __shfl_xor_sync(0xffffffffu, acc[e], o);

    if (lane == 0) {
        float m = acc[0];
#pragma unroll
        for (int e = 1; e < E_; e++) m = fmaxf(m, acc[e]);
        float p[E_]; float s = 0.f;
#pragma unroll
        for (int e = 0; e < E_; e++) { p[e] = __expf(acc[e] - m); s += p[e]; }
        float inv = 1.f / s;
#pragma unroll
        for (int e = 0; e < E_; e++) p[e] *= inv;
        int i0 = 0; float v0 = p[0];
#pragma unroll
        for (int e = 1; e < E_; e++) if (p[e] > v0) { v0 = p[e]; i0 = e; }
        int i1 = -1; float v1 = -1.f;
#pragma unroll
        for (int e = 0; e < E_; e++) if (e != i0 && p[e] > v1) { v1 = p[e]; i1 = e; }
        g_top[t * 2] = i0;  g_top[t * 2 + 1] = i1;
        g_wgt[t * 2] = v0;  g_wgt[t * 2 + 1] = v1;
        atomicAdd(&g_counts[i0], 1);
        atomicAdd(&g_counts[i1], 1);
    }
}

__global__ void k_offs() {
    if (threadIdx.x == 0) {
        int s = 0;
        for (int e = 0; e < E_; e++) { g_offs[e] = s; s += g_counts[e]; g_cursor[e] = 0; }
        g_offs[E_] = s;
    }
}

__global__ void k_scatter(int T) {
    int i = blockIdx.x * blockDim.x + threadIdx.x;
    if (i >= T * 2) return;
    int t = i >> 1;
    int e = g_top[i];
    int pos = atomicAdd(&g_cursor[e], 1);
    int idx = g_offs[e] + pos;
    g_bucket[idx] = t;
    g_bw[idx] = g_wgt[i];
}

// ======================================================================
// fc1: tiled bf16-split MMA.  CTA computes 128 rows x 64 features, with
// y/gate weight rows interleaved so each thread's C column pair is (y, g)
// of the same feature; SiLU fused at epilogue, act written as bf16 hi/lo.
// ======================================================================
template <bool ROUTED>
__global__ __launch_bounds__(256)
void k_fc1t(const __nv_bfloat16* __restrict__ Ahg, const __nv_bfloat16* __restrict__ Alg,
            const __nv_bfloat16* __restrict__ Whg, const __nv_bfloat16* __restrict__ Wlg,
            __nv_bfloat16* __restrict__ Oh, __nv_bfloat16* __restrict__ Ol,
            int T, int hid) {
    extern __shared__ __nv_bfloat16 sm[];
    __shared__ int toks[128];

    int mcount, rbase;
    const __nv_bfloat16 *Wh, *Wl;
    if (ROUTED) {
        int e = blockIdx.z;
        rbase = g_offs[e];
        mcount = g_offs[e + 1] - rbase;
        size_t wo = (size_t)e * 2 * hid * D_;
        Wh = Whg + wo; Wl = Wlg + wo;
    } else { mcount = T; rbase = 0; Wh = Whg; Wl = Wlg; }
    int m0 = blockIdx.x * 128;
    if (m0 >= mcount) return;
    int n0f = blockIdx.y * 64;
    int tid = threadIdx.x;

    if (tid < 128) {
        int r = m0 + tid; if (r > mcount - 1) r = mcount - 1;
        toks[tid] = ROUTED ? g_bucket[rbase + r] : r;
    }
    __syncthreads();

    uint32_t sbase = cvta_s(sm);
    const int K = D_;
    const int nst = K / KSZ;

    auto load_stage = [&](int s) {
        uint32_t sb = sbase + (uint32_t)(s & 1) * (STAGE_ELEMS * 2);
        int k0 = s * KSZ;
#pragma unroll
        for (int j = 0; j < 8; j++) {
            int c = tid + 256 * j;
            int mat = c >> 9;
            int rc = c & 511;
            int row = rc >> 2;
            int ch = rc & 3;
            uint32_t dst = sb + (uint32_t)(mat * 128 * STR + row * STR + ch * 8) * 2;
            const __nv_bfloat16* src;
            if (mat < 2) {
                const __nv_bfloat16* base = (mat == 0) ? Ahg : Alg;
                src = base + (size_t)toks[row] * K + k0 + ch * 8;
            } else {
                int f = n0f + (row >> 1);
                int srow = (row & 1) ? (hid + f) : f;
                const __nv_bfloat16* base = (mat == 2) ? Wh : Wl;
                src = base + (size_t)srow * K + k0 + ch * 8;
            }
            CPA(dst, src);
        }
        CPC();
    };

    int wid = tid >> 5, lane = tid & 31;
    int wm = wid >> 2, wn = wid & 3;

    float c[4][4][4];
#pragma unroll
    for (int a = 0; a < 4; a++)
#pragma unroll
        for (int b = 0; b < 4; b++)
#pragma unroll
            for (int d = 0; d < 4; d++) c[a][b][d] = 0.f;

    int arow = wm * 64 + (lane & 15);
    int acol0 = (lane >> 4) * 8;
    int g8 = lane >> 3;
    int brin = lane & 7;

    load_stage(0);
    for (int s = 0; s < nst; s++) {
        if (s + 1 < nst) { load_stage(s + 1); CPW1(); } else { CPW0(); }
        __syncthreads();
        uint32_t sb = sbase + (uint32_t)(s & 1) * (STAGE_ELEMS * 2);
        uint32_t Ahb = sb;
        uint32_t Alb = sb + 128 * STR * 2;
        uint32_t Bhb = sb + 2 * 128 * STR * 2;
        uint32_t Blb = sb + 3 * 128 * STR * 2;
#pragma unroll
        for (int ks = 0; ks < 2; ks++) {
            uint32_t ah[4][4], al[4][4], bh[4][2], bl[4][2];
#pragma unroll
            for (int mi = 0; mi < 4; mi++) {
                uint32_t off = (uint32_t)((arow + mi * 16) * STR + ks * 16 + acol0) * 2;
                LDM4(ah[mi][0], ah[mi][1], ah[mi][2], ah[mi][3], Ahb + off);
                LDM4(al[mi][0], al[mi][1], al[mi][2], al[mi][3], Alb + off);
            }
#pragma unroll
            for (int j2 = 0; j2 < 2; j2++) {
                int nf = j2 * 2 + (g8 >> 1);
                uint32_t off = (uint32_t)((wn * 32 + nf * 8 + brin) * STR + ks * 16 + (g8 & 1) * 8) * 2;
                uint32_t r0, r1, r2, r3;
                LDM4(r0, r1, r2, r3, Bhb + off);
                bh[j2 * 2][0] = r0; bh[j2 * 2][1] = r1; bh[j2 * 2 + 1][0] = r2; bh[j2 * 2 + 1][1] = r3;
                LDM4(r0, r1, r2, r3, Blb + off);
                bl[j2 * 2][0] = r0; bl[j2 * 2][1] = r1; bl[j2 * 2 + 1][0] = r2; bl[j2 * 2 + 1][1] = r3;
            }
#pragma unroll
            for (int mi = 0; mi < 4; mi++)
#pragma unroll
                for (int nj = 0; nj < 4; nj++) {
                    MMA(c[mi][nj], ah[mi], bh[nj]);
                    MMA(c[mi][nj], ah[mi], bl[nj]);
                    MMA(c[mi][nj], al[mi], bh[nj]);
                }
        }
        __syncthreads();
    }

    int rrem = mcount - m0;
#pragma unroll
    for (int mi = 0; mi < 4; mi++)
#pragma unroll
        for (int half = 0; half < 2; half++) {
            int row = wm * 64 + mi * 16 + (lane >> 2) + half * 8;
            if (row < rrem) {
                size_t rb = (size_t)(rbase + m0 + row) * hid;
#pragma unroll
                for (int nj = 0; nj < 4; nj++) {
                    float y = c[mi][nj][half * 2 + 0];
                    float g = c[mi][nj][half * 2 + 1];
                    float a = y * g / (1.f + __expf(-g));
                    int f = n0f + wn * 16 + nj * 4 + (lane & 3);
                    __nv_bfloat16 h = __float2bfloat16(a);
                    Oh[rb + f] = h;
                    Ol[rb + f] = __float2bfloat16(a - __bfloat162float(h));
                }
            }
        }
}

// ======================================================================
// fc2: 128x128 bf16-split GEMM tile; routed rows combine via atomicAdd
// scaled by routing weight, shared rows store directly.
// ======================================================================
template <bool ROUTED>
__global__ __launch_bounds__(256)
void k_fc2t(const __nv_bfloat16* __restrict__ Ahg, const __nv_bfloat16* __restrict__ Alg,
            const __nv_bfloat16* __restrict__ Whg, const __nv_bfloat16* __restrict__ Wlg,
            float* __restrict__ out, int T, int hid) {
    extern __shared__ __nv_bfloat16 sm[];
    __shared__ int toks[128];
    __shared__ float bws[128];

    int mcount, rbase;
    const __nv_bfloat16 *Wh, *Wl;
    if (ROUTED) {
        int e = blockIdx.z;
        rbase = g_offs[e];
        mcount = g_offs[e + 1] - rbase;
        size_t wo = (size_t)e * D_ * hid;
        Wh = Whg + wo; Wl = Wlg + wo;
    } else { mcount = T; rbase = 0; Wh = Whg; Wl = Wlg; }
    int m0 = blockIdx.x * 128;
    if (m0 >= mcount) return;
    int n0 = blockIdx.y * 128;
    int tid = threadIdx.x;

    if (ROUTED && tid < 128) {
        int r = m0 + tid; if (r > mcount - 1) r = mcount - 1;
        toks[tid] = g_bucket[rbase + r];
        bws[tid] = g_bw[rbase + r];
    }
    __syncthreads();

    uint32_t sbase = cvta_s(sm);
    const int K = hid;
    const int nst = K / KSZ;

    auto load_stage = [&](int s) {
        uint32_t sb = sbase + (uint32_t)(s & 1) * (STAGE_ELEMS * 2);
        int k0 = s * KSZ;
#pragma unroll
        for (int j = 0; j < 8; j++) {
            int c = tid + 256 * j;
            int mat = c >> 9;
            int rc = c & 511;
            int row = rc >> 2;
            int ch = rc & 3;
            uint32_t dst = sb + (uint32_t)(mat * 128 * STR + row * STR + ch * 8) * 2;
            const __nv_bfloat16* src;
            if (mat < 2) {
                int ar = m0 + row; if (ar > mcount - 1) ar = mcount - 1;
                const __nv_bfloat16* base = (mat == 0) ? Ahg : Alg;
                src = base + (size_t)(rbase + ar) * K + k0 + ch * 8;
            } else {
                const __nv_bfloat16* base = (mat == 2) ? Wh : Wl;
                src = base + (size_t)(n0 + row) * K + k0 + ch * 8;
            }
            CPA(dst, src);
        }
        CPC();
    };

    int wid = tid >> 5, lane = tid & 31;
    int wm = wid >> 2, wn = wid & 3;

    float c[4][4][4];
#pragma unroll
    for (int a = 0; a < 4; a++)
#pragma unroll
        for (int b = 0; b < 4; b++)
#pragma unroll
            for (int d = 0; d < 4; d++) c[a][b][d] = 0.f;

    int arow = wm * 64 + (lane & 15);
    int acol0 = (lane >> 4) * 8;
    int g8 = lane >> 3;
    int brin = lane & 7;

    load_stage(0);
    for (int s = 0; s < nst; s++) {
        if (s + 1 < nst) { load_stage(s + 1); CPW1(); } else { CPW0(); }
        __syncthreads();
        uint32_t sb = sbase + (uint32_t)(s & 1) * (STAGE_ELEMS * 2);
        uint32_t Ahb = sb;
        uint32_t Alb = sb + 128 * STR * 2;
        uint32_t Bhb = sb + 2 * 128 * STR * 2;
        uint32_t Blb = sb + 3 * 128 * STR * 2;
#pragma unroll
        for (int ks = 0; ks < 2; ks++) {
            uint32_t ah[4][4], al[4][4], bh[4][2], bl[4][2];
#pragma unroll
            for (int mi = 0; mi < 4; mi++) {
                uint32_t off = (uint32_t)((arow + mi * 16) * STR + ks * 16 + acol0) * 2;
                LDM4(ah[mi][0], ah[mi][1], ah[mi][2], ah[mi][3], Ahb + off);
                LDM4(al[mi][0], al[mi][1], al[mi][2], al[mi][3], Alb + off);
            }
#pragma unroll
            for (int j2 = 0; j2 < 2; j2++) {
                int nf = j2 * 2 + (g8 >> 1);
                uint32_t off = (uint32_t)((wn * 32 + nf * 8 + brin) * STR + ks * 16 + (g8 & 1) * 8) * 2;
                uint32_t r0, r1, r2, r3;
                LDM4(r0, r1, r2, r3, Bhb + off);
                bh[j2 * 2][0] = r0; bh[j2 * 2][1] = r1; bh[j2 * 2 + 1][0] = r2; bh[j2 * 2 + 1][1] = r3;
                LDM4(r0, r1, r2, r3, Blb + off);
                bl[j2 * 2][0] = r0; bl[j2 * 2][1] = r1; bl[j2 * 2 + 1][0] = r2; bl[j2 * 2 + 1][1] = r3;
            }
#pragma unroll
            for (int mi = 0; mi < 4; mi++)
#pragma unroll
                for (int nj = 0; nj < 4; nj++) {
                    MMA(c[mi][nj], ah[mi], bh[nj]);
                    MMA(c[mi][nj], ah[mi], bl[nj]);
                    MMA(c[mi][nj], al[mi], bh[nj]);
                }
        }
        __syncthreads();
    }

    int rrem = mcount - m0;
#pragma unroll
    for (int mi = 0; mi < 4; mi++)
#pragma unroll
        for (int half = 0; half < 2; half++) {
            int row = wm * 64 + mi * 16 + (lane >> 2) + half * 8;
            if (row < rrem) {
#pragma unroll
                for (int nj = 0; nj < 4; nj++) {
                    int col = n0 + wn * 32 + nj * 8 + (lane & 3) * 2;
                    float v0 = c[mi][nj][half * 2 + 0];
                    float v1 = c[mi][nj][half * 2 + 1];
                    if (ROUTED) {
                        int t = toks[row]; float w = bws[row];
                        atomicAdd(out + (size_t)t * D_ + col, w * v0);
                        atomicAdd(out + (size_t)t * D_ + col + 1, w * v1);
                    } else {
                        *(float2*)(out + (size_t)(m0 + row) * D_ + col) = make_float2(v0, v1);
                    }
                }
            }
        }
}

// ---------------- launcher ----------------
extern "C" void kernel_launch(void* const* d_in, const int* in_sizes, int n_in,
                              void* d_out, int out_size) {
    const float* x   = (const float*)d_in[0];
    const float* gw  = (const float*)d_in[1];
    const float* W1  = (const float*)d_in[2];
    const float* W2  = (const float*)d_in[3];
    const float* Ws1 = (const float*)d_in[4];
    const float* Ws2 = (const float*)d_in[5];
    float* out = (float*)d_out;

    int T = in_sizes[0] / D_;
    if (T > TMAX) T = TMAX;

    // symbol addresses
    __nv_bfloat16 *xh, *xl, *W1h, *W1l, *W2h, *W2l, *S1h, *S1l, *S2h, *S2l, *aRh, *aRl, *aSh, *aSl;
    cudaGetSymbolAddress((void**)&xh,  g_xh);  cudaGetSymbolAddress((void**)&xl,  g_xl);
    cudaGetSymbolAddress((void**)&W1h, g_W1h); cudaGetSymbolAddress((void**)&W1l, g_W1l);
    cudaGetSymbolAddress((void**)&W2h, g_W2h); cudaGetSymbolAddress((void**)&W2l, g_W2l);
    cudaGetSymbolAddress((void**)&S1h, g_S1h); cudaGetSymbolAddress((void**)&S1l, g_S1l);
    cudaGetSymbolAddress((void**)&S2h, g_S2h); cudaGetSymbolAddress((void**)&S2l, g_S2l);
    cudaGetSymbolAddress((void**)&aRh, g_aRh); cudaGetSymbolAddress((void**)&aRl, g_aRl);
    cudaGetSymbolAddress((void**)&aSh, g_aSh); cudaGetSymbolAddress((void**)&aSl, g_aSl);

    cudaFuncSetAttribute(k_fc1t<true>,  cudaFuncAttributeMaxDynamicSharedMemorySize, SMEM_BYTES);
    cudaFuncSetAttribute(k_fc1t<false>, cudaFuncAttributeMaxDynamicSharedMemorySize, SMEM_BYTES);
    cudaFuncSetAttribute(k_fc2t<true>,  cudaFuncAttributeMaxDynamicSharedMemorySize, SMEM_BYTES);
    cudaFuncSetAttribute(k_fc2t<false>, cudaFuncAttributeMaxDynamicSharedMemorySize, SMEM_BYTES);

    // conversions (fp32 -> bf16 hi/lo)
    auto cvt = [&](const float* s, __nv_bfloat16* h, __nv_bfloat16* l, size_t n) {
        int n4 = (int)(n / 4);
        k_cvt<<<(n4 + 255) / 256, 256>>>(s, h, l, n4);
    };
    cvt(x,   xh,  xl,  (size_t)T * D_);
    cvt(W1,  W1h, W1l, (size_t)E_ * 2 * H_ * D_);
    cvt(W2,  W2h, W2l, (size_t)E_ * D_ * H_);
    cvt(Ws1, S1h, S1l, (size_t)2 * HS_ * D_);
    cvt(Ws2, S2h, S2l, (size_t)D_ * HS_);

    // routing
    k_zero<<<1, 32>>>();
    k_gate<<<(T + 7) / 8, 256>>>(x, gw, T);
    k_offs<<<1, 32>>>();
    k_scatter<<<(T * 2 + 255) / 256, 256>>>(T);

    int mt = (T + 127) / 128;

    // fc1
    k_fc1t<true ><<<dim3(mt, H_  / 64, E_), 256, SMEM_BYTES>>>(xh, xl, W1h, W1l, aRh, aRl, T, H_);
    k_fc1t<false><<<dim3(mt, HS_ / 64),     256, SMEM_BYTES>>>(xh, xl, S1h, S1l, aSh, aSl, T, HS_);

    // fc2: shared (stores) first, then routed (atomic accumulate)
    k_fc2t<false><<<dim3(mt, D_ / 128),     256, SMEM_BYTES>>>(aSh, aSl, S2h, S2l, out, T, HS_);
    k_fc2t<true ><<<dim3(mt, D_ / 128, E_), 256, SMEM_BYTES>>>(aRh, aRl, W2h, W2l, out, T, H_);
}